// round 2
// baseline (speedup 1.0000x reference)
#include <cuda_runtime.h>
#include <math.h>

// BayesRingRNN collapses exactly to a 2-scalar recurrence per batch:
// r_i(t) = u(t)*cos(phi_i) + v(t)*sin(phi_i)   (rank-2 weights, r0 in span).
//
// Phase 1 (chain):  latency-bound serial recurrence -> traj[b][t] = (u,v)
// Phase 2 (expand): bandwidth-bound outer-product expansion to (B,T,N)

#define NN 80
#define TT 1500
#define MAXB 1024

__device__ float2 g_traj[(size_t)MAXB * TT];   // 12.3 MB scratch (fits in L2)

// ---------------------------------------------------------------- phase 1 --
__global__ void __launch_bounds__(128, 8)
chain_kernel(const float* __restrict__ inputs,   // (B,T,2)
             const float* __restrict__ phi,      // (N,)
             float* __restrict__ out,            // tail: r_final (1,B,N)
             int B, float kz, long long out_size)
{
    const int b    = (blockIdx.x * blockDim.x + threadIdx.x) >> 5;
    const int lane = threadIdx.x & 31;
    if (b >= B) return;

    // KP=1, KV=2, DT=0.01:
    const float C1   = 0.01f / 3.0f;                 // sqrt-term coeff
    const float C0C2 = 1.0f - 0.01f / 3.0f + 0.01f / 3.0f; // (1-ALPHA*DT) + DT*a_even
    const float C3   = 2.0f / 3.0f;                  // a_odd

    float u = 10.0f;   // r0 = 10*cos(phi) -> (u,v)=(10,0) exactly
    float v = 0.0f;

    const float2* inp = reinterpret_cast<const float2*>(inputs) + (size_t)b * TT;
    float2* tr = g_traj + (size_t)b * TT;

    for (int t = 0; t < TT; t += 32) {
        const int chunk = min(32, TT - t);
        // per-lane precompute (off the serial critical path)
        float kc = 0.f, ks = 0.f, gi = 0.f;
        if (lane < chunk) {
            float2 x = inp[t + lane];
            float s, c; sincosf(x.x, &s, &c);
            kc = kz * c; ks = kz * s; gi = C3 * x.y;
        }
        float su = u, sv = v;
        #pragma unroll 4
        for (int j = 0; j < chunk; ++j) {
            const float gij = __shfl_sync(0xffffffffu, gi, j);
            const float kcj = __shfl_sync(0xffffffffu, kc, j);
            const float ksj = __shfl_sync(0xffffffffu, ks, j);

            const float m = sqrtf(fmaf(u, u, v * v));
            const float d = fmaf(-C1, m, C0C2);
            const float nu = fmaf(d, u, fmaf(-gij, v, kcj));
            const float nv = fmaf(d, v, fmaf( gij, u, ksj));
            u = nu; v = nv;
            if (j == lane) { su = u; sv = v; }
        }
        if (lane < chunk) tr[t + lane] = make_float2(su, sv);
    }

    // r_final appended after the (B,T,N) block
    const long long base = (long long)B * TT * NN;
    if (out_size >= base + (long long)B * NN) {
        float* fp = out + base + (size_t)b * NN;
        float s, c;
        sincosf(phi[lane], &s, &c);        fp[lane]      = fmaf(v, s, u * c);
        sincosf(phi[lane + 32], &s, &c);   fp[lane + 32] = fmaf(v, s, u * c);
        if (lane < NN - 64) {
            sincosf(phi[lane + 64], &s, &c); fp[lane + 64] = fmaf(v, s, u * c);
        }
    }
}

// ---------------------------------------------------------------- phase 2 --
__global__ void __launch_bounds__(256)
expand_kernel(const float* __restrict__ phi, float* __restrict__ out, int total4)
{
    __shared__ float4 c4[NN / 4], s4[NN / 4];
    if (threadIdx.x < NN) {
        float s, c; sincosf(phi[threadIdx.x], &s, &c);
        reinterpret_cast<float*>(c4)[threadIdx.x] = c;
        reinterpret_cast<float*>(s4)[threadIdx.x] = s;
    }
    __syncthreads();

    float4* __restrict__ o4 = reinterpret_cast<float4*>(out);
    const int stride = gridDim.x * blockDim.x;

    for (int i = blockIdx.x * blockDim.x + threadIdx.x; i < total4; i += stride) {
        const int bt  = i / (NN / 4);          // mul-shift, 32-bit
        const int rem = i - bt * (NN / 4);
        const float2 uv = g_traj[bt];          // L2-resident (written by phase 1)
        const float4 c = c4[rem];
        const float4 s = s4[rem];
        float4 o;
        o.x = fmaf(uv.y, s.x, uv.x * c.x);
        o.y = fmaf(uv.y, s.y, uv.x * c.y);
        o.z = fmaf(uv.y, s.z, uv.x * c.z);
        o.w = fmaf(uv.y, s.w, uv.x * c.w);
        o4[i] = o;
    }
}

// --- host-side exact replica of the reference's _xi_inv (double precision) --
static double xi_f(double a, double target)
{
    const double x = (a / 2.0) * (a / 2.0);
    double t0 = 1.0, t1 = a / 2.0;
    double i0 = t0, i1 = t1;
    for (int k = 1; k < 30; ++k) {
        t0 *= x / ((double)k * (double)k);
        t1 *= x / ((double)k * (double)(k + 1));
        i0 += t0;
        i1 += t1;
    }
    return a * i1 / i0 - target;
}

static float compute_kappa_z()
{
    const double target = 15.0 * 0.01;
    double lo = 1e-3, hi = 50.0;
    for (int i = 0; i < 200; ++i) {
        const double mid = 0.5 * (lo + hi);
        if (xi_f(lo, target) * xi_f(mid, target) <= 0.0) hi = mid;
        else lo = mid;
    }
    return (float)(0.5 * (lo + hi));
}

extern "C" void kernel_launch(void* const* d_in, const int* in_sizes, int n_in,
                              void* d_out, int out_size)
{
    const float* inputs = (const float*)d_in[0];  // (B,T,2)
    const float* phi    = (const float*)d_in[4];  // (N,)
    float* out = (float*)d_out;

    int B = in_sizes[0] / (2 * TT);
    if (B > MAXB) B = MAXB;
    const float kz = compute_kappa_z();

    // Phase 1: serial chains, warp per batch
    {
        const int threads = 128;
        const int blocks = (B * 32 + threads - 1) / threads;
        chain_kernel<<<blocks, threads>>>(inputs, phi, out, B, kz, (long long)out_size);
    }
    // Phase 2: bandwidth-bound expansion
    {
        const int total4 = B * TT * (NN / 4);   // 30.72M float4 stores
        const int threads = 256;
        const int blocks = 1184;                // grid-stride, ~8 CTAs/SM
        expand_kernel<<<blocks, threads>>>(phi, out, total4);
    }
}